// round 1
// baseline (speedup 1.0000x reference)
#include <cuda_runtime.h>
#include <cuda_bf16.h>
#include <stdint.h>

// Problem constants (fixed by setup_inputs)
#define NNODE 1024          // "num_edges" n in the reference = node count here
#define SD 8                // stalk dim
#define DD 64               // 8*8
#define OUTDIM 8192         // n*d
#define EPSV 1e-4f
#define NS_ITERS 18

// Scratch (static device globals; no allocation allowed)
__device__ float g_diag[NNODE * DD];     // segment-sum of F^T F per source node
__device__ float g_dis[NNODE * DD];      // D^{-1/2} per node
__device__ int   g_tab[NNODE * NNODE];   // (i,j) -> edge index, else -1

// ---------------------------------------------------------------------------
// K0a: zero the 256MB output (vectorized)
__global__ void k_zero_out(float4* __restrict__ out, long n4) {
    long idx = (long)blockIdx.x * blockDim.x + threadIdx.x;
    long stride = (long)gridDim.x * blockDim.x;
    float4 z = make_float4(0.f, 0.f, 0.f, 0.f);
    for (long i = idx; i < n4; i += stride) out[i] = z;
}

// K0b: init small scratch: table = -1, diag = 0
__global__ void k_init_small() {
    int idx = blockIdx.x * blockDim.x + threadIdx.x;
    int stride = gridDim.x * blockDim.x;
    for (int i = idx; i < NNODE * NNODE; i += stride) g_tab[i] = -1;
    for (int i = idx; i < NNODE * DD; i += stride) g_diag[i] = 0.f;
}

// K1: scatter edge indices into the lookup table
__global__ void k_scatter(const int* __restrict__ E, int P) {
    int p = blockIdx.x * blockDim.x + threadIdx.x;
    if (p < P) {
        int i = E[2 * p], j = E[2 * p + 1];
        g_tab[i * NNODE + j] = p;
    }
}

// K2: FtF[p] = R_p^T R_p, atomically accumulated into g_diag[src]
// 4 edges per 256-thread block; 64 threads per edge (one per matrix element).
__global__ void k_ftf(const float* __restrict__ R, const int* __restrict__ E, int P) {
    __shared__ float sR[4 * DD];
    int t = threadIdx.x;
    int e0 = blockIdx.x * 4;
    int pl = t >> 6, el = t & 63;
    int p = e0 + pl;
    if (p < P) sR[t] = R[(long)e0 * DD + t];
    __syncthreads();
    if (p >= P) return;
    int i = el >> 3, j = el & 7;
    float v = 0.f;
#pragma unroll
    for (int k = 0; k < 8; k++) v += sR[pl * DD + k * 8 + i] * sR[pl * DD + k * 8 + j];
    int src = E[2 * p];
    atomicAdd(&g_diag[src * DD + el], v);
}

// K3: per-node: D = sym(diag)+eps*I ; Dis = D^{-1/2} via coupled Newton-Schulz.
// Also writes the diagonal output block Dis * diag_raw * Dis.
// 4 nodes per 256-thread block, 64 threads per node.
__global__ void k_node(float* __restrict__ out) {
    __shared__ float sD[4][DD], sY[4][DD], sZ[4][DD], sT[4][DD];
    int t = threadIdx.x;
    int ln = t >> 6, el = t & 63;
    int i = el >> 3, j = el & 7;
    int node = blockIdx.x * 4 + ln;

    float draw = g_diag[node * DD + el];
    sD[ln][el] = draw;
    __syncthreads();

    // symmetrize + eps
    float dsym = 0.5f * (sD[ln][el] + sD[ln][j * 8 + i]) + ((i == j) ? EPSV : 0.f);
    // trace of D (all threads compute same value)
    float c = 8.0f * EPSV;
#pragma unroll
    for (int k = 0; k < 8; k++) c += sD[ln][k * 8 + k];
    float inv_c = 1.0f / c;

    __syncthreads();
    sY[ln][el] = dsym * inv_c;            // Abar, eigenvalues in (0,1]
    sZ[ln][el] = (i == j) ? 1.f : 0.f;    // -> Abar^{-1/2}
    __syncthreads();

    for (int it = 0; it < NS_ITERS; it++) {
        float tv = 0.f;
#pragma unroll
        for (int k = 0; k < 8; k++) tv += sZ[ln][i * 8 + k] * sY[ln][k * 8 + j];
        __syncthreads();
        sT[ln][el] = tv;
        __syncthreads();
        float yv = 0.f, zv = 0.f;
#pragma unroll
        for (int k = 0; k < 8; k++) {
            yv += sY[ln][i * 8 + k] * sT[ln][k * 8 + j];
            zv += sT[ln][i * 8 + k] * sZ[ln][k * 8 + j];
        }
        yv = 1.5f * sY[ln][el] - 0.5f * yv;
        zv = 1.5f * sZ[ln][el] - 0.5f * zv;
        __syncthreads();
        sY[ln][el] = yv;
        sZ[ln][el] = zv;
        __syncthreads();
    }

    float dis = sZ[ln][el] * rsqrtf(c);
    // symmetrize Dis (exact fixpoint is symmetric; removes fp drift)
    __syncthreads();
    sT[ln][el] = dis;
    __syncthreads();
    dis = 0.5f * (sT[ln][el] + sT[ln][j * 8 + i]);
    g_dis[node * DD + el] = dis;

    // diagonal output block: Dis * diag_raw * Dis
    __syncthreads();
    sZ[ln][el] = dis;
    __syncthreads();
    float b1 = 0.f;
#pragma unroll
    for (int k = 0; k < 8; k++) b1 += sZ[ln][i * 8 + k] * sD[ln][k * 8 + j];
    __syncthreads();
    sT[ln][el] = b1;
    __syncthreads();
    float b2 = 0.f;
#pragma unroll
    for (int k = 0; k < 8; k++) b2 += sT[ln][i * 8 + k] * sZ[ln][k * 8 + j];
    out[(long)(node * 8 + i) * OUTDIM + node * 8 + j] = b2;
}

// K4: per-edge off-diagonal block:
//   M  = -sign(L1[i,j]) * F_ji^T * F_ij        (zero if reverse edge missing)
//   out_block(i,j) = Dis_i * M * Dis_j
// 4 edges per 256-thread block.
__global__ void k_edge(const float* __restrict__ R, const int* __restrict__ E,
                       const float* __restrict__ L1, float* __restrict__ out, int P) {
    __shared__ float sA[4][DD], sB[4][DD], sDi[4][DD], sDj[4][DD];
    __shared__ float ssgn[4];
    __shared__ int srev[4];
    int t = threadIdx.x;
    int ln = t >> 6, el = t & 63;
    int i = el >> 3, j = el & 7;
    int p = blockIdx.x * 4 + ln;
    bool active = (p < P);

    int ni = 0, nj = 0;
    if (active) {
        ni = E[2 * p];
        nj = E[2 * p + 1];
        if (el == 0) {
            srev[ln] = g_tab[nj * NNODE + ni];
            float x = L1[(long)ni * NNODE + nj];
            // msgn = -sign(x)
            ssgn[ln] = (x > 0.f) ? -1.f : ((x < 0.f) ? 1.f : 0.f);
        }
    }
    __syncthreads();

    float m = 0.f;
    if (active) {
        int rev = srev[ln];
        sA[ln][el] = R[(long)p * DD + el];
        sB[ln][el] = (rev >= 0) ? R[(long)rev * DD + el] : 0.f;
        sDi[ln][el] = g_dis[ni * DD + el];
        sDj[ln][el] = g_dis[nj * DD + el];
    }
    __syncthreads();
    if (active) {
        float msgn = ssgn[ln];
#pragma unroll
        for (int k = 0; k < 8; k++) m += sB[ln][k * 8 + i] * sA[ln][k * 8 + j];
        m *= msgn;
    }
    __syncthreads();
    if (active) sA[ln][el] = m;   // reuse sA as M
    __syncthreads();
    float m2 = 0.f;
    if (active) {
#pragma unroll
        for (int k = 0; k < 8; k++) m2 += sDi[ln][i * 8 + k] * sA[ln][k * 8 + j];
    }
    __syncthreads();
    if (active) sA[ln][el] = m2;
    __syncthreads();
    if (active) {
        float m3 = 0.f;
#pragma unroll
        for (int k = 0; k < 8; k++) m3 += sA[ln][i * 8 + k] * sDj[ln][k * 8 + j];
        out[(long)(ni * 8 + i) * OUTDIM + nj * 8 + j] = m3;
    }
}

// ---------------------------------------------------------------------------
extern "C" void kernel_launch(void* const* d_in, const int* in_sizes, int n_in,
                              void* d_out, int out_size) {
    const float* R = (const float*)d_in[0];
    const int* E = (const int*)d_in[1];
    // L1 is the input with n*n elements (robust to scalar num_edges placement)
    const float* L1 = nullptr;
    for (int k = 2; k < n_in; k++) {
        if (in_sizes[k] == NNODE * NNODE) { L1 = (const float*)d_in[k]; break; }
    }
    if (!L1) L1 = (const float*)d_in[n_in - 1];

    float* out = (float*)d_out;
    int P = in_sizes[1] / 2;

    long n4 = (long)out_size / 4;
    k_zero_out<<<8192, 256>>>((float4*)out, n4);
    k_init_small<<<2048, 256>>>();
    k_scatter<<<(P + 255) / 256, 256>>>(E, P);
    k_ftf<<<(P + 3) / 4, 256>>>(R, E, P);
    k_node<<<NNODE / 4, 256>>>(out);
    k_edge<<<(P + 3) / 4, 256>>>(R, E, L1, out, P);
}